// round 1
// baseline (speedup 1.0000x reference)
#include <cuda_runtime.h>
#include <cuda_bf16.h>
#include <math.h>

// ---------------------------------------------------------------------------
// T6Attention (tensor-product attention) — fp32 baseline
// B=2, S=2048, D_MODEL=1024, HEADS=16, DK=64, Q_RANK=6, RANK=2
// Pipeline:
//   1) 6 projections (tiled SGEMM)      A_q,A_k,A_v,B_q,B_k,B_v
//   2) RoPE in-place on B_q, B_k
//   3) rank contractions -> qh,kh,vh    [B*H][S][DK]
//   4) causal flash attention (online softmax), out in [B][S][H*DK]
//   5) output projection SGEMM -> d_out
// ---------------------------------------------------------------------------

#define BATCH     2
#define SEQ       2048
#define DMODEL    1024
#define HEADS     16
#define DK        64
#define QRANK     6
#define RANK      2
#define NTOK      (BATCH*SEQ)        // 4096
#define BH        (BATCH*HEADS)      // 32

// scratch offsets (floats)
#define OFF_AQ   0
#define SZ_AQ    (NTOK*HEADS*QRANK)          // 393216
#define OFF_AK   (OFF_AQ+SZ_AQ)
#define SZ_AK    (NTOK*HEADS*RANK)           // 131072
#define OFF_AV   (OFF_AK+SZ_AK)
#define SZ_AV    SZ_AK
#define OFF_BQ   (OFF_AV+SZ_AV)
#define SZ_BQ    (NTOK*QRANK*DK)             // 1572864
#define OFF_BK   (OFF_BQ+SZ_BQ)
#define SZ_BK    (NTOK*RANK*DK)              // 524288
#define OFF_BV   (OFF_BK+SZ_BK)
#define SZ_BV    SZ_BK
#define OFF_QH   (OFF_BV+SZ_BV)
#define SZ_QH    (BH*SEQ*DK)                 // 4194304
#define OFF_KH   (OFF_QH+SZ_QH)
#define OFF_VH   (OFF_KH+SZ_QH)
#define OFF_OA   (OFF_VH+SZ_QH)
#define SCRATCH_TOTAL (OFF_OA+SZ_QH)         // 20054016 floats ~ 80MB

__device__ float g_scratch[SCRATCH_TOTAL];

// ---------------------------------------------------------------------------
// Tiled SGEMM: C[M,N] = A[M,K] @ W[K,N], all row-major. K % 8 == 0, M % 128 == 0.
// BM=128, BN=64, BK=8, 256 threads, each thread 8x4.
// ---------------------------------------------------------------------------
#define GBM 128
#define GBN 64
#define GBK 8

__global__ __launch_bounds__(256) void gemm_kernel(
    const float* __restrict__ A, const float* __restrict__ W,
    float* __restrict__ C, int M, int N, int K)
{
    __shared__ float As[GBK][GBM];
    __shared__ float Ws[GBK][GBN];

    const int tid = threadIdx.x;
    const int tx = tid & 15;     // 0..15 -> 4 cols each
    const int ty = tid >> 4;     // 0..15 -> 8 rows each
    const int m0 = blockIdx.y * GBM;
    const int n0 = blockIdx.x * GBN;

    float acc[8][4];
#pragma unroll
    for (int i = 0; i < 8; i++)
#pragma unroll
        for (int j = 0; j < 4; j++) acc[i][j] = 0.f;

    for (int k0 = 0; k0 < K; k0 += GBK) {
        // load A tile: 128x8 = 1024 elems, 4 per thread
#pragma unroll
        for (int i = 0; i < 4; i++) {
            int idx = tid + i * 256;
            int mm = idx >> 3;
            int kk = idx & 7;
            As[kk][mm] = A[(size_t)(m0 + mm) * K + k0 + kk];
        }
        // load W tile: 8x64 = 512 elems, 2 per thread
#pragma unroll
        for (int i = 0; i < 2; i++) {
            int idx = tid + i * 256;
            int kk = idx >> 6;
            int nn = idx & 63;
            int gn = n0 + nn;
            Ws[kk][nn] = (gn < N) ? W[(size_t)(k0 + kk) * N + gn] : 0.f;
        }
        __syncthreads();

#pragma unroll
        for (int kk = 0; kk < GBK; kk++) {
            float a[8], b[4];
#pragma unroll
            for (int i = 0; i < 8; i++) a[i] = As[kk][ty * 8 + i];
#pragma unroll
            for (int j = 0; j < 4; j++) b[j] = Ws[kk][tx * 4 + j];
#pragma unroll
            for (int i = 0; i < 8; i++)
#pragma unroll
                for (int j = 0; j < 4; j++) acc[i][j] += a[i] * b[j];
        }
        __syncthreads();
    }

#pragma unroll
    for (int i = 0; i < 8; i++) {
        int gm = m0 + ty * 8 + i;
#pragma unroll
        for (int j = 0; j < 4; j++) {
            int gn = n0 + tx * 4 + j;
            if (gn < N) C[(size_t)gm * N + gn] = acc[i][j];
        }
    }
}

// ---------------------------------------------------------------------------
// RoPE in-place on X[NTOK][R][DK]: half-split rotary, dim 64 (d=32 pairs)
// ---------------------------------------------------------------------------
__global__ void rope_kernel(float* __restrict__ X, int R, int total)
{
    int idx = blockIdx.x * blockDim.x + threadIdx.x;
    if (idx >= total) return;
    int i = idx & 31;                 // pair index 0..31
    int r = (idx >> 5) % R;
    int t = idx / (32 * R);
    int s = t & (SEQ - 1);            // position within sequence

    float inv_freq = powf(10000.0f, -(float)(2 * i) / 64.0f);
    float fr = (float)s * inv_freq;
    float sn, cs;
    sincosf(fr, &sn, &cs);

    float* base = X + ((size_t)t * R + r) * DK;
    float x1 = base[i];
    float x2 = base[32 + i];
    base[i]      = x1 * cs + x2 * sn;
    base[32 + i] = -x1 * sn + x2 * cs;
}

// ---------------------------------------------------------------------------
// Rank contraction: out[(b*H+h)][s][d] = scale * sum_r A[t][h*R+r]*Bm[t][r*DK+d]
// ---------------------------------------------------------------------------
__global__ void contract_kernel(const float* __restrict__ Am,
                                const float* __restrict__ Bm,
                                float* __restrict__ out, int R, float scale)
{
    int idx = blockIdx.x * blockDim.x + threadIdx.x;
    if (idx >= NTOK * HEADS * DK) return;
    int d = idx & (DK - 1);
    int h = (idx >> 6) & (HEADS - 1);
    int t = idx >> 10;

    const float* a = Am + (size_t)t * (HEADS * R) + h * R;
    const float* b = Bm + (size_t)t * R * DK + d;
    float s = 0.f;
#pragma unroll 6
    for (int r = 0; r < R; r++) s += a[r] * b[r * DK];

    int bb = t >> 11;                // t / SEQ
    int ss = t & (SEQ - 1);
    out[(((size_t)(bb * HEADS + h)) * SEQ + ss) * DK + d] = s * scale;
}

// ---------------------------------------------------------------------------
// Causal flash attention.
// grid (SEQ/64, B*H), 64 threads/block. Thread t owns query row qt*64+t.
// score = (q . k) / DK, causal mask, online softmax in fp32.
// Output written to [B][S][H*DK] layout ready for the Wo GEMM.
// ---------------------------------------------------------------------------
__global__ __launch_bounds__(64) void flash_kernel(
    const float* __restrict__ Qh, const float* __restrict__ Kh,
    const float* __restrict__ Vh, float* __restrict__ O)
{
    const int bh = blockIdx.y;
    const int qt = blockIdx.x;
    const int t = threadIdx.x;           // 0..63
    const int qrow = qt * 64 + t;

    __shared__ float4 Ks4[64][16];
    __shared__ float4 Vs4[64][16];

    // q row -> registers, pre-scaled by 1/DK
    float qreg[64];
    {
        const float4* qp4 = reinterpret_cast<const float4*>(
            Qh + ((size_t)bh * SEQ + qrow) * DK);
        const float inv_dk = 1.0f / (float)DK;
#pragma unroll
        for (int d4 = 0; d4 < 16; d4++) {
            float4 qq = qp4[d4];
            qreg[4 * d4 + 0] = qq.x * inv_dk;
            qreg[4 * d4 + 1] = qq.y * inv_dk;
            qreg[4 * d4 + 2] = qq.z * inv_dk;
            qreg[4 * d4 + 3] = qq.w * inv_dk;
        }
    }

    float4 acc4[16];
#pragma unroll
    for (int d4 = 0; d4 < 16; d4++) acc4[d4] = make_float4(0.f, 0.f, 0.f, 0.f);
    float m = -INFINITY, l = 0.f;

    for (int kt = 0; kt <= qt; kt++) {
        __syncthreads();
        const float4* kb4 = reinterpret_cast<const float4*>(
            Kh + ((size_t)bh * SEQ + kt * 64) * DK);
        const float4* vb4 = reinterpret_cast<const float4*>(
            Vh + ((size_t)bh * SEQ + kt * 64) * DK);
#pragma unroll
        for (int i = 0; i < 16; i++) {
            int idx = i * 64 + t;
            Ks4[idx >> 4][idx & 15] = kb4[idx];
            Vs4[idx >> 4][idx & 15] = vb4[idx];
        }
        __syncthreads();

        const int kg0 = kt * 64;
        for (int c = 0; c < 4; c++) {
            float p[16];
            float mloc = -INFINITY;
#pragma unroll
            for (int j = 0; j < 16; j++) {
                const int jj = c * 16 + j;
                float a0 = 0.f, a1 = 0.f, a2 = 0.f, a3 = 0.f;
#pragma unroll
                for (int d4 = 0; d4 < 16; d4++) {
                    float4 kk4 = Ks4[jj][d4];
                    a0 += qreg[4 * d4 + 0] * kk4.x;
                    a1 += qreg[4 * d4 + 1] * kk4.y;
                    a2 += qreg[4 * d4 + 2] * kk4.z;
                    a3 += qreg[4 * d4 + 3] * kk4.w;
                }
                float sv = (a0 + a1) + (a2 + a3);
                if (kg0 + jj > qrow) sv = -INFINITY;
                p[j] = sv;
                mloc = fmaxf(mloc, sv);
            }
            float m_new = fmaxf(m, mloc);
            float factor = __expf(m - m_new);
            float psum = 0.f;
#pragma unroll
            for (int j = 0; j < 16; j++) {
                p[j] = __expf(p[j] - m_new);
                psum += p[j];
            }
            l = l * factor + psum;
            m = m_new;
#pragma unroll
            for (int d4 = 0; d4 < 16; d4++) {
                acc4[d4].x *= factor; acc4[d4].y *= factor;
                acc4[d4].z *= factor; acc4[d4].w *= factor;
            }
#pragma unroll
            for (int j = 0; j < 16; j++) {
                const float pj = p[j];
#pragma unroll
                for (int d4 = 0; d4 < 16; d4++) {
                    float4 vv = Vs4[c * 16 + j][d4];
                    acc4[d4].x += pj * vv.x;
                    acc4[d4].y += pj * vv.y;
                    acc4[d4].z += pj * vv.z;
                    acc4[d4].w += pj * vv.w;
                }
            }
        }
    }

    const int b = bh >> 4;
    const int h = bh & 15;
    const float inv_l = 1.0f / l;
    float4* op4 = reinterpret_cast<float4*>(
        O + ((size_t)(b * SEQ) + qrow) * DMODEL + h * DK);
#pragma unroll
    for (int d4 = 0; d4 < 16; d4++) {
        float4 a = acc4[d4];
        op4[d4] = make_float4(a.x * inv_l, a.y * inv_l, a.z * inv_l, a.w * inv_l);
    }
}

// ---------------------------------------------------------------------------
extern "C" void kernel_launch(void* const* d_in, const int* in_sizes, int n_in,
                              void* d_out, int out_size)
{
    const float* q    = (const float*)d_in[0];
    const float* k    = (const float*)d_in[1];
    const float* v    = (const float*)d_in[2];
    // d_in[3] = mask (causal, reconstructed analytically; unused)
    const float* W_Aq = (const float*)d_in[4];
    const float* W_Ak = (const float*)d_in[5];
    const float* W_Av = (const float*)d_in[6];
    const float* W_Bq = (const float*)d_in[7];
    const float* W_Bk = (const float*)d_in[8];
    const float* W_Bv = (const float*)d_in[9];
    const float* Wo   = (const float*)d_in[10];
    float* out = (float*)d_out;

    float* scratch = nullptr;
    cudaGetSymbolAddress((void**)&scratch, g_scratch);
    float* sAq = scratch + OFF_AQ;
    float* sAk = scratch + OFF_AK;
    float* sAv = scratch + OFF_AV;
    float* sBq = scratch + OFF_BQ;
    float* sBk = scratch + OFF_BK;
    float* sBv = scratch + OFF_BV;
    float* sQh = scratch + OFF_QH;
    float* sKh = scratch + OFF_KH;
    float* sVh = scratch + OFF_VH;
    float* sOa = scratch + OFF_OA;

    // 1) projections
    {
        dim3 blk(256);
        gemm_kernel<<<dim3((96   + GBN - 1) / GBN, NTOK / GBM), blk>>>(q, W_Aq, sAq, NTOK, 96, DMODEL);
        gemm_kernel<<<dim3((32   + GBN - 1) / GBN, NTOK / GBM), blk>>>(k, W_Ak, sAk, NTOK, 32, DMODEL);
        gemm_kernel<<<dim3((32   + GBN - 1) / GBN, NTOK / GBM), blk>>>(v, W_Av, sAv, NTOK, 32, DMODEL);
        gemm_kernel<<<dim3((384  + GBN - 1) / GBN, NTOK / GBM), blk>>>(q, W_Bq, sBq, NTOK, 384, DMODEL);
        gemm_kernel<<<dim3((128  + GBN - 1) / GBN, NTOK / GBM), blk>>>(k, W_Bk, sBk, NTOK, 128, DMODEL);
        gemm_kernel<<<dim3((128  + GBN - 1) / GBN, NTOK / GBM), blk>>>(v, W_Bv, sBv, NTOK, 128, DMODEL);
    }

    // 2) RoPE on B_q, B_k
    {
        int total_q = NTOK * QRANK * 32;
        int total_k = NTOK * RANK * 32;
        rope_kernel<<<(total_q + 255) / 256, 256>>>(sBq, QRANK, total_q);
        rope_kernel<<<(total_k + 255) / 256, 256>>>(sBk, RANK, total_k);
    }

    // 3) rank contractions -> qh, kh, vh
    {
        int total = NTOK * HEADS * DK;
        contract_kernel<<<(total + 255) / 256, 256>>>(sAq, sBq, sQh, QRANK, 1.0f / QRANK);
        contract_kernel<<<(total + 255) / 256, 256>>>(sAk, sBk, sKh, RANK, 1.0f / RANK);
        contract_kernel<<<(total + 255) / 256, 256>>>(sAv, sBv, sVh, RANK, 1.0f / RANK);
    }

    // 4) causal flash attention
    flash_kernel<<<dim3(SEQ / 64, BH), 64>>>(sQh, sKh, sVh, sOa);

    // 5) output projection
    gemm_kernel<<<dim3(DMODEL / GBN, NTOK / GBM), 256>>>(sOa, Wo, out, NTOK, DMODEL, DMODEL);
}